// round 10
// baseline (speedup 1.0000x reference)
#include <cuda_runtime.h>
#include <cuda_fp16.h>
#include <cstdint>

// Problem constants
#define M_DIM 8192
#define K_DIM 4096
#define N_DIM 11008
#define NP    (N_DIM / 8)

// tcgen05 GEMM: CTA tile 256x256, BK=64, 3 stages, warp-specialized,
// B dequantized int4 -> fp16 in-kernel into K-MAJOR smem (proven descriptor).
#define BM 256
#define BN 256
#define BK 64
#define STAGE_A_BYTES (BM * BK * 2)                     // 32768
#define STAGE_B_BYTES (BN * BK * 2)                     // 32768
#define STAGE_BYTES   (STAGE_A_BYTES + STAGE_B_BYTES)   // 65536
#define SMEM_STAGES   (3 * STAGE_BYTES)                 // 196608
#define SMEM_TOTAL    (SMEM_STAGES + 1024 + 128)

// Static device scratch
__device__ __half g_X[(size_t)M_DIM * K_DIM];   // activations fp16

// ---------------------------------------------------------------------------
__device__ __forceinline__ void cp_async16(uint32_t smem, const void* gmem) {
    asm volatile("cp.async.cg.shared.global [%0], [%1], 16;\n"
                 :: "r"(smem), "l"(gmem) : "memory");
}
// Pack two fp32 -> fp16x2 (lo=f0, hi=f1)
__device__ __forceinline__ uint32_t pack_f16x2(float f0, float f1) {
    uint32_t r;
    asm("cvt.rn.f16x2.f32 %0, %1, %2;" : "=r"(r) : "f"(f1), "f"(f0));
    return r;
}

// ---------------------------------------------------------------------------
// Pass 0: x fp32 -> fp16 (lossless; harness upcast of original fp16)
// ---------------------------------------------------------------------------
__global__ void convert_x_kernel(const float* __restrict__ x, int total) {
    int i = (blockIdx.x * blockDim.x + threadIdx.x) * 4;
    if (i >= total) return;
    float4 v = *reinterpret_cast<const float4*>(x + i);
    __half h[4];
    h[0] = __float2half(v.x); h[1] = __float2half(v.y);
    h[2] = __float2half(v.z); h[3] = __float2half(v.w);
    *reinterpret_cast<uint2*>(&g_X[i]) = *reinterpret_cast<uint2*>(h);
}

// ---------------------------------------------------------------------------
// tcgen05 helpers (device pass targets sm_103a family)
// ---------------------------------------------------------------------------
#if defined(__CUDA_ARCH__) && (defined(__CUDA_ARCH_FEAT_SM103_ALL) || defined(__CUDA_ARCH_FEAT_SM100_ALL) || defined(__CUDA_ARCH_FEAT_SM101_ALL))
#define TC_LIVE 1
#endif

#ifdef TC_LIVE
__device__ __forceinline__ uint32_t elect_one() {
    uint32_t p;
    asm volatile("{\n\t.reg .pred P;\n\telect.sync _|P, 0xFFFFFFFF;\n\t"
                 "selp.b32 %0, 1, 0, P;\n\t}" : "=r"(p));
    return p;
}
__device__ __forceinline__ void mbar_init(uint32_t a, uint32_t cnt) {
    asm volatile("mbarrier.init.shared.b64 [%0], %1;" :: "r"(a), "r"(cnt) : "memory");
}
__device__ __forceinline__ void mbar_wait(uint32_t a, uint32_t parity) {
    asm volatile("{\n\t.reg .pred P;\n\tLW%=:\n\t"
                 "mbarrier.try_wait.parity.acquire.cta.shared::cta.b64 P, [%0], %1;\n\t"
                 "@!P bra LW%=;\n\t}" :: "r"(a), "r"(parity) : "memory");
}
__device__ __forceinline__ void mbar_arrive(uint32_t a) {
    asm volatile("mbarrier.arrive.release.cta.shared::cta.b64 _, [%0];"
                 :: "r"(a) : "memory");
}
__device__ __forceinline__ void cpasync_arrive_noinc(uint32_t a) {
    asm volatile("cp.async.mbarrier.arrive.noinc.shared.b64 [%0];"
                 :: "r"(a) : "memory");
}
__device__ __forceinline__ void fence_proxy_async_cta() {
    asm volatile("fence.proxy.async.shared::cta;" ::: "memory");
}
__device__ __forceinline__ void tc_commit(uint32_t mbar) {
    asm volatile("tcgen05.commit.cta_group::1.mbarrier::arrive::one.shared::cluster.b64 [%0];"
                 :: "r"(mbar) : "memory");
}
__device__ __forceinline__ void mma_f16_ss(uint32_t d, uint64_t ad, uint64_t bd,
                                           uint32_t idesc, uint32_t en) {
    asm volatile("{\n\t.reg .pred p;\n\tsetp.ne.u32 p, %4, 0;\n\t"
                 "tcgen05.mma.cta_group::1.kind::f16 [%0], %1, %2, %3, {%5,%5,%5,%5}, p;\n\t}"
                 :: "r"(d), "l"(ad), "l"(bd), "r"(idesc), "r"(en), "r"(0u) : "memory");
}
// K-major SW128 descriptor: layout=2, version=1, SBO=64, LBO=1 (proven)
__device__ __forceinline__ uint64_t make_desc(uint32_t smem_addr) {
    return ((uint64_t)2 << 61) | ((uint64_t)1 << 46) | ((uint64_t)64 << 32) |
           ((uint64_t)1 << 16) | (((uint64_t)(smem_addr >> 4)) & 0x3FFF);
}
__device__ __forceinline__ void ldtm_x32(uint32_t* r, uint32_t tmem) {
    asm volatile(
        "tcgen05.ld.sync.aligned.32x32b.x32.b32 "
        "{%0,%1,%2,%3,%4,%5,%6,%7,%8,%9,%10,%11,%12,%13,%14,%15,"
        "%16,%17,%18,%19,%20,%21,%22,%23,%24,%25,%26,%27,%28,%29,%30,%31}, [%32];"
        : "=r"(r[0]),"=r"(r[1]),"=r"(r[2]),"=r"(r[3]),"=r"(r[4]),"=r"(r[5]),"=r"(r[6]),"=r"(r[7]),
          "=r"(r[8]),"=r"(r[9]),"=r"(r[10]),"=r"(r[11]),"=r"(r[12]),"=r"(r[13]),"=r"(r[14]),"=r"(r[15]),
          "=r"(r[16]),"=r"(r[17]),"=r"(r[18]),"=r"(r[19]),"=r"(r[20]),"=r"(r[21]),"=r"(r[22]),"=r"(r[23]),
          "=r"(r[24]),"=r"(r[25]),"=r"(r[26]),"=r"(r[27]),"=r"(r[28]),"=r"(r[29]),"=r"(r[30]),"=r"(r[31])
        : "r"(tmem));
}
#endif  // TC_LIVE

// 288 threads: warps 0-7 = producers (A cp.async + B int4 dequant-transpose),
// warp 8 = MMA issuer.
__global__ __launch_bounds__(288, 1)
void gemm_tc_kernel(const int* __restrict__ qweight,
                    const int* __restrict__ qzeros,
                    const float* __restrict__ scales,
                    float* __restrict__ Out) {
#ifdef TC_LIVE
    extern __shared__ char smem_raw[];
    char* smem = (char*)(((uintptr_t)smem_raw + 1023) & ~(uintptr_t)1023);
    const uint32_t sbase = (uint32_t)__cvta_generic_to_shared(smem);
    const uint32_t mbarb = sbase + SMEM_STAGES;
    // full_cp[s]: +0,+8,+16 ; full_st[s]: +24,+32,+40 ; empty[s]: +48,+56,+64
    // fin: +72 ; tmem ptr: +80

    const int tid  = threadIdx.x;
    const int wid  = tid >> 5;
    const int lane = tid & 31;
    const int bm = blockIdx.x * BM;
    const int bn = blockIdx.y * BN;

    if (tid == 0) {
#pragma unroll
        for (int s = 0; s < 3; s++) {
            mbar_init(mbarb +      8 * s, 256);  // full_cp
            mbar_init(mbarb + 24 + 8 * s, 256);  // full_st
            mbar_init(mbarb + 48 + 8 * s, 1);    // empty
        }
        mbar_init(mbarb + 72, 1);                // fin
    }
    if (wid == 8) {
        asm volatile("tcgen05.alloc.cta_group::1.sync.aligned.shared::cta.b32 [%0], %1;"
                     :: "r"(mbarb + 80), "r"(512) : "memory");
        asm volatile("tcgen05.relinquish_alloc_permit.cta_group::1.sync.aligned;");
    }
    __syncthreads();
    uint32_t tmem;
    asm volatile("ld.shared.b32 %0, [%1];" : "=r"(tmem) : "r"(mbarb + 80));

    const int KT = K_DIM / BK;  // 64

    if (wid < 8) {
        // ---------------- producer warps (256 threads) ----------------
        // Lane owns 8 consecutive n (packed col c_idx) x 8 consecutive k (octet=wid).
        const int c_idx = lane;              // packed col in CTA tile (32 = 256 n)
        const int ko    = wid;               // k-octet 0..7 (k = ko*8..ko*8+7)
        const size_t qcol = (size_t)(bn >> 3) + c_idx;

        float s_f[8], ns_f[8];               // pre-rotated scale / -zero*scale
        uint32_t wq[8], wq2[8];

        // Prologue: qweight for chunk 0
#pragma unroll
        for (int r = 0; r < 8; r++)
            wq[r] = (uint32_t)qweight[(size_t)(ko * 8 + r) * NP + qcol];

        for (int kt = 0; kt < KT; kt++) {
            const int s = kt % 3;
            const uint32_t e_par = ((kt / 3) & 1) ^ 1;   // first 3 uses pass
            mbar_wait(mbarb + 48 + 8 * s, e_par);

            // Prefetch qweight for next chunk (overlaps with dequant below)
            if (kt + 1 < KT) {
                const int k0n = (kt + 1) * BK;
#pragma unroll
                for (int r = 0; r < 8; r++)
                    wq2[r] = (uint32_t)qweight[(size_t)(k0n + ko * 8 + r) * NP + qcol];
            }

            if ((kt & 1) == 0) {             // group changes every 2 chunks
                const int g = kt >> 1;
                uint32_t z = (uint32_t)qzeros[(size_t)g * NP + qcol];
                const float* sp = scales + (size_t)g * N_DIM + bn + c_idx * 8;
#pragma unroll
                for (int jj = 0; jj < 8; jj++) {
                    int jr = (jj + lane) & 7;        // pre-rotated index
                    float sv = sp[jr];
                    s_f[jj]  = sv;
                    ns_f[jj] = -sv * (float)((z >> (4 * jr)) & 15u);
                }
            }

            uint32_t a_s = sbase + s * STAGE_BYTES;
            uint32_t b_s = a_s + STAGE_A_BYTES;

            // ---- B: register-transpose dequant into K-MAJOR SW128 smem ----
            // Row n_local (128B, 64 k-halves), swizzle phase n_local & 7.
#pragma unroll
            for (int jj = 0; jj < 8; jj++) {
                const int j = (jj + lane) & 7;       // rotation kills bank conflicts
                const int sh = 4 * j;
                uint32_t h2[4];
#pragma unroll
                for (int p = 0; p < 4; p++) {
                    float f0 = fmaf((float)((wq[2*p]   >> sh) & 15u), s_f[jj], ns_f[jj]);
                    float f1 = fmaf((float)((wq[2*p+1] >> sh) & 15u), s_f[jj], ns_f[jj]);
                    h2[p] = pack_f16x2(f0, f1);
                }
                const int n_local = c_idx * 8 + j;   // n_local & 7 == j
                uint32_t addr = b_s + n_local * 128 + ((uint32_t)(ko ^ j) << 4);
                asm volatile("st.shared.v4.b32 [%0], {%1,%2,%3,%4};"
                             :: "r"(addr), "r"(h2[0]), "r"(h2[1]), "r"(h2[2]), "r"(h2[3])
                             : "memory");
            }
            fence_proxy_async_cta();          // generic-proxy STS -> async proxy
            mbar_arrive(mbarb + 24 + 8 * s);  // release B

            // ---- A: cp.async 8 x 16B per thread ----
            const __half* Ag = g_X + (size_t)bm * K_DIM + kt * BK;
#pragma unroll
            for (int i = 0; i < 8; i++) {
                int idx = tid + 256 * i;       // 0..2047
                int row = idx >> 3, c16 = idx & 7;
                cp_async16(a_s + row * 128 + ((c16 ^ (row & 7)) << 4),
                           Ag + (size_t)row * K_DIM + c16 * 8);
            }
            cpasync_arrive_noinc(mbarb + 8 * s);

#pragma unroll
            for (int r = 0; r < 8; r++) wq[r] = wq2[r];
        }
    } else if (elect_one()) {
        // ---------------- MMA issuer (1 thread of warp 8) ----------------
        // Proven round-6 config: M=128, N=128, f16 in, f32 acc, both K-major.
        const uint32_t idesc = (8u << 24) | (16u << 17) | (1u << 4);
        for (int kt = 0; kt < KT; kt++) {
            const int s = kt % 3;
            const uint32_t par = (kt / 3) & 1;
            mbar_wait(mbarb +      8 * s, par);   // A cp.async complete
            mbar_wait(mbarb + 24 + 8 * s, par);   // B STS complete
            fence_proxy_async_cta();

            uint32_t a_s = sbase + s * STAGE_BYTES;
            uint32_t b_s = a_s + STAGE_A_BYTES;
            uint64_t ad0 = make_desc(a_s);
            uint64_t ad1 = make_desc(a_s + 16384);
            uint64_t bd0 = make_desc(b_s);
            uint64_t bd1 = make_desc(b_s + 16384);
#pragma unroll
            for (int ks = 0; ks < 4; ks++) {
                uint32_t en = (kt > 0 || ks > 0) ? 1u : 0u;
                mma_f16_ss(tmem,       ad0 + ks * 2, bd0 + ks * 2, idesc, en);
                mma_f16_ss(tmem + 128, ad0 + ks * 2, bd1 + ks * 2, idesc, en);
                mma_f16_ss(tmem + 256, ad1 + ks * 2, bd0 + ks * 2, idesc, en);
                mma_f16_ss(tmem + 384, ad1 + ks * 2, bd1 + ks * 2, idesc, en);
            }
            tc_commit(mbarb + 48 + 8 * s);     // recycle stage on MMA completion
        }
        tc_commit(mbarb + 72);
    }

    // All threads: wait for all MMAs to drain
    mbar_wait(mbarb + 72, 0);
    asm volatile("tcgen05.fence::after_thread_sync;" ::: "memory");

    // Epilogue (warps 0-7): warp w -> M-half (w>>2), rows (w&3)*32
    if (wid < 8) {
        const int h   = wid >> 2;
        const int row = bm + h * 128 + (wid & 3) * 32 + lane;
        float* dst = Out + (size_t)row * N_DIM + bn;
        const uint32_t tm = tmem + h * 256;
#pragma unroll
        for (int b = 0; b < 8; b++) {
            uint32_t v[32];
            ldtm_x32(v, tm + b * 32);
            asm volatile("tcgen05.wait::ld.sync.aligned;" ::: "memory");
#pragma unroll
            for (int i = 0; i < 8; i++) {
                float4 f;
                f.x = __uint_as_float(v[4 * i + 0]);
                f.y = __uint_as_float(v[4 * i + 1]);
                f.z = __uint_as_float(v[4 * i + 2]);
                f.w = __uint_as_float(v[4 * i + 3]);
                *reinterpret_cast<float4*>(dst + b * 32 + i * 4) = f;
            }
        }
    }
    __syncthreads();
    if (wid == 8) {
        asm volatile("tcgen05.dealloc.cta_group::1.sync.aligned.b32 %0, %1;"
                     :: "r"(tmem), "r"(512));
    }
#endif  // TC_LIVE
}

// ---------------------------------------------------------------------------
extern "C" void kernel_launch(void* const* d_in, const int* in_sizes, int n_in,
                              void* d_out, int out_size) {
    const float* x  = (const float*)d_in[0];   // [4,2048,4096] fp32 (upcast fp16)
    const int*   qw = (const int*)d_in[1];     // [4096,1376]
    const int*   qz = (const int*)d_in[2];     // [32,1376]
    const float* sc = (const float*)d_in[3];   // [32,11008] fp32 (upcast fp16)
    float* out = (float*)d_out;                // [4,2048,11008] fp32

    cudaFuncSetAttribute(gemm_tc_kernel, cudaFuncAttributeMaxDynamicSharedMemorySize,
                         SMEM_TOTAL);

    const int x_total = in_sizes[0];
    convert_x_kernel<<<(x_total / 4 + 255) / 256, 256>>>(x, x_total);

    dim3 grid(M_DIM / BM, N_DIM / BN);         // (32, 43)
    gemm_tc_kernel<<<grid, 288, SMEM_TOTAL>>>(qw, qz, sc, out);
}

// round 11
// speedup vs baseline: 1.0324x; 1.0324x over previous
#include <cuda_runtime.h>
#include <cuda_fp16.h>
#include <cstdint>

// Problem constants
#define M_DIM 8192
#define K_DIM 4096
#define N_DIM 11008
#define NP    (N_DIM / 8)

// tcgen05 GEMM: CTA tile 256x256, BK=64, 3 stages, warp-specialized,
// B dequantized int4 -> fp16 in-kernel via LOP3 magic numbers, K-major smem.
#define BM 256
#define BN 256
#define BK 64
#define STAGE_A_BYTES (BM * BK * 2)                     // 32768
#define STAGE_B_BYTES (BN * BK * 2)                     // 32768
#define STAGE_BYTES   (STAGE_A_BYTES + STAGE_B_BYTES)   // 65536
#define SMEM_STAGES   (3 * STAGE_BYTES)                 // 196608
#define SMEM_TOTAL    (SMEM_STAGES + 1024 + 128)

// Static device scratch
__device__ __half g_X[(size_t)M_DIM * K_DIM];   // activations fp16

// ---------------------------------------------------------------------------
__device__ __forceinline__ void cp_async16(uint32_t smem, const void* gmem) {
    asm volatile("cp.async.cg.shared.global [%0], [%1], 16;\n"
                 :: "r"(smem), "l"(gmem) : "memory");
}

// ---------------------------------------------------------------------------
// Pass 0: x fp32 -> fp16 (lossless; harness upcast of original fp16)
// ---------------------------------------------------------------------------
__global__ void convert_x_kernel(const float* __restrict__ x, int total) {
    int i = (blockIdx.x * blockDim.x + threadIdx.x) * 4;
    if (i >= total) return;
    float4 v = *reinterpret_cast<const float4*>(x + i);
    __half h[4];
    h[0] = __float2half(v.x); h[1] = __float2half(v.y);
    h[2] = __float2half(v.z); h[3] = __float2half(v.w);
    *reinterpret_cast<uint2*>(&g_X[i]) = *reinterpret_cast<uint2*>(h);
}

// ---------------------------------------------------------------------------
// tcgen05 helpers (device pass targets sm_103a family)
// ---------------------------------------------------------------------------
#if defined(__CUDA_ARCH__) && (defined(__CUDA_ARCH_FEAT_SM103_ALL) || defined(__CUDA_ARCH_FEAT_SM100_ALL) || defined(__CUDA_ARCH_FEAT_SM101_ALL))
#define TC_LIVE 1
#endif

#ifdef TC_LIVE
__device__ __forceinline__ uint32_t elect_one() {
    uint32_t p;
    asm volatile("{\n\t.reg .pred P;\n\telect.sync _|P, 0xFFFFFFFF;\n\t"
                 "selp.b32 %0, 1, 0, P;\n\t}" : "=r"(p));
    return p;
}
__device__ __forceinline__ void mbar_init(uint32_t a, uint32_t cnt) {
    asm volatile("mbarrier.init.shared.b64 [%0], %1;" :: "r"(a), "r"(cnt) : "memory");
}
__device__ __forceinline__ void mbar_wait(uint32_t a, uint32_t parity) {
    asm volatile("{\n\t.reg .pred P;\n\tLW%=:\n\t"
                 "mbarrier.try_wait.parity.acquire.cta.shared::cta.b64 P, [%0], %1;\n\t"
                 "@!P bra LW%=;\n\t}" :: "r"(a), "r"(parity) : "memory");
}
__device__ __forceinline__ void mbar_arrive(uint32_t a) {
    asm volatile("mbarrier.arrive.release.cta.shared::cta.b64 _, [%0];"
                 :: "r"(a) : "memory");
}
__device__ __forceinline__ void cpasync_arrive_noinc(uint32_t a) {
    asm volatile("cp.async.mbarrier.arrive.noinc.shared.b64 [%0];"
                 :: "r"(a) : "memory");
}
__device__ __forceinline__ void fence_proxy_async_cta() {
    asm volatile("fence.proxy.async.shared::cta;" ::: "memory");
}
__device__ __forceinline__ void tc_commit(uint32_t mbar) {
    asm volatile("tcgen05.commit.cta_group::1.mbarrier::arrive::one.shared::cluster.b64 [%0];"
                 :: "r"(mbar) : "memory");
}
__device__ __forceinline__ void mma_f16_ss(uint32_t d, uint64_t ad, uint64_t bd,
                                           uint32_t idesc, uint32_t en) {
    asm volatile("{\n\t.reg .pred p;\n\tsetp.ne.u32 p, %4, 0;\n\t"
                 "tcgen05.mma.cta_group::1.kind::f16 [%0], %1, %2, %3, {%5,%5,%5,%5}, p;\n\t}"
                 :: "r"(d), "l"(ad), "l"(bd), "r"(idesc), "r"(en), "r"(0u) : "memory");
}
// K-major SW128 descriptor: layout=2, version=1, SBO=64, LBO=1 (proven)
__device__ __forceinline__ uint64_t make_desc(uint32_t smem_addr) {
    return ((uint64_t)2 << 61) | ((uint64_t)1 << 46) | ((uint64_t)64 << 32) |
           ((uint64_t)1 << 16) | (((uint64_t)(smem_addr >> 4)) & 0x3FFF);
}
__device__ __forceinline__ void ldtm_x32(uint32_t* r, uint32_t tmem) {
    asm volatile(
        "tcgen05.ld.sync.aligned.32x32b.x32.b32 "
        "{%0,%1,%2,%3,%4,%5,%6,%7,%8,%9,%10,%11,%12,%13,%14,%15,"
        "%16,%17,%18,%19,%20,%21,%22,%23,%24,%25,%26,%27,%28,%29,%30,%31}, [%32];"
        : "=r"(r[0]),"=r"(r[1]),"=r"(r[2]),"=r"(r[3]),"=r"(r[4]),"=r"(r[5]),"=r"(r[6]),"=r"(r[7]),
          "=r"(r[8]),"=r"(r[9]),"=r"(r[10]),"=r"(r[11]),"=r"(r[12]),"=r"(r[13]),"=r"(r[14]),"=r"(r[15]),
          "=r"(r[16]),"=r"(r[17]),"=r"(r[18]),"=r"(r[19]),"=r"(r[20]),"=r"(r[21]),"=r"(r[22]),"=r"(r[23]),
          "=r"(r[24]),"=r"(r[25]),"=r"(r[26]),"=r"(r[27]),"=r"(r[28]),"=r"(r[29]),"=r"(r[30]),"=r"(r[31])
        : "r"(tmem));
}
#endif  // TC_LIVE

// 288 threads: warps 0-7 = producers (A cp.async + B lop3 dequant-transpose),
// warp 8 = MMA issuer.
__global__ __launch_bounds__(288, 1)
void gemm_tc_kernel(const int* __restrict__ qweight,
                    const int* __restrict__ qzeros,
                    const float* __restrict__ scales,
                    float* __restrict__ Out) {
#ifdef TC_LIVE
    extern __shared__ char smem_raw[];
    char* smem = (char*)(((uintptr_t)smem_raw + 1023) & ~(uintptr_t)1023);
    const uint32_t sbase = (uint32_t)__cvta_generic_to_shared(smem);
    const uint32_t mbarb = sbase + SMEM_STAGES;
    // full_cp[s]: +0,+8,+16 ; full_st[s]: +24,+32,+40 ; empty[s]: +48,+56,+64
    // fin: +72 ; tmem ptr: +80

    const int tid  = threadIdx.x;
    const int wid  = tid >> 5;
    const int lane = tid & 31;
    const int bm = blockIdx.x * BM;
    const int bn = blockIdx.y * BN;

    if (tid == 0) {
#pragma unroll
        for (int s = 0; s < 3; s++) {
            mbar_init(mbarb +      8 * s, 256);  // full_cp
            mbar_init(mbarb + 24 + 8 * s, 256);  // full_st
            mbar_init(mbarb + 48 + 8 * s, 1);    // empty
        }
        mbar_init(mbarb + 72, 1);                // fin
    }
    if (wid == 8) {
        asm volatile("tcgen05.alloc.cta_group::1.sync.aligned.shared::cta.b32 [%0], %1;"
                     :: "r"(mbarb + 80), "r"(512) : "memory");
        asm volatile("tcgen05.relinquish_alloc_permit.cta_group::1.sync.aligned;");
    }
    __syncthreads();
    uint32_t tmem;
    asm volatile("ld.shared.b32 %0, [%1];" : "=r"(tmem) : "r"(mbarb + 80));

    const int KT = K_DIM / BK;  // 64

    if (wid < 8) {
        // ---------------- producer warps (256 threads) ----------------
        // Lane owns 8 consecutive n (packed col = lane) x 8 consecutive k
        // (octet = wid). Nibble rotation by (lane&7) + k-pair rotation by
        // (lane>>3) make every STS.32 bank-conflict free with STATIC regs.
        const int L  = lane & 7;            // nibble rotation
        const int pr = lane >> 3;           // k-pair rotation
        const int ko = wid;                 // k-octet
        const size_t qcol = (size_t)(bn >> 3) + lane;

        uint32_t zc[4];                      // extraction constants (z folded)
        uint32_t s2lo[4], s2hi[4];           // broadcast fp16x2 scales per row
        uint32_t wq[8], wq2[8];

        // qweight row for register slot r=2q+e: ko*8 + 2*((q+pr)&3) + e
        int krow[4];
#pragma unroll
        for (int q = 0; q < 4; q++) krow[q] = ko * 8 + 2 * ((q + pr) & 3);

        // Prologue: load chunk 0 qweight
#pragma unroll
        for (int q = 0; q < 4; q++) {
            wq[2*q]   = (uint32_t)qweight[(size_t)(krow[q])     * NP + qcol];
            wq[2*q+1] = (uint32_t)qweight[(size_t)(krow[q] + 1) * NP + qcol];
        }

        for (int kt = 0; kt < KT; kt++) {
            const int s = kt % 3;
            const uint32_t e_par = ((kt / 3) & 1) ^ 1;   // first 3 uses pass
            mbar_wait(mbarb + 48 + 8 * s, e_par);

            // Prefetch next chunk's qweight (hides under dequant)
            if (kt + 1 < KT) {
                const int k0n = (kt + 1) * BK;
#pragma unroll
                for (int q = 0; q < 4; q++) {
                    wq2[2*q]   = (uint32_t)qweight[(size_t)(k0n + krow[q])     * NP + qcol];
                    wq2[2*q+1] = (uint32_t)qweight[(size_t)(k0n + krow[q] + 1) * NP + qcol];
                }
            }

            if ((kt & 1) == 0) {             // group changes every 2 chunks
                const int g = kt >> 1;
                uint32_t zw = (uint32_t)qzeros[(size_t)g * NP + qcol];
                uint32_t zr  = __funnelshift_r(zw, zw, L * 4);
                uint32_t zr8 = zr >> 8;
                zc[0] = 0x64006400u + (zr  & 0x000F000Fu);  // {1024+z_j} pairs
                zc[1] = 0xD400D400u + (zr  & 0x00F000F0u);  // {-(64+z_j)} pairs
                zc[2] = 0x64006400u + (zr8 & 0x000F000Fu);
                zc[3] = 0xD400D400u + (zr8 & 0x00F000F0u);
                const float* sp = scales + (size_t)g * N_DIM + bn + lane * 8;
#pragma unroll
                for (int c = 0; c < 4; c++) {
                    int jlo = (c + L) & 7;
                    uint32_t uslo = (uint32_t)__half_as_ushort(__float2half(sp[jlo]));
                    uint32_t ushi = (uint32_t)__half_as_ushort(__float2half(sp[jlo ^ 4]));
                    s2lo[c] = uslo * 0x10001u;
                    s2hi[c] = ushi * 0x10001u;
                }
            }

            uint32_t a_s = sbase + s * STAGE_BYTES;
            uint32_t b_s = a_s + STAGE_A_BYTES;

            // ---- B: LOP3 magic dequant, register transpose, K-major STS ----
            uint32_t rot[8], rh[8];
#pragma unroll
            for (int r = 0; r < 8; r++) {
                rot[r] = __funnelshift_r(wq[r], wq[r], L * 4);
                rh[r]  = rot[r] >> 8;
            }
#pragma unroll
            for (int c = 0; c < 4; c++) {
                const uint32_t mask = (c & 1) ? 0x00F000F0u : 0x000F000Fu;
                uint32_t e[8];
#pragma unroll
                for (int r = 0; r < 8; r++) {
                    uint32_t src = (c < 2) ? rot[r] : rh[r];
                    asm("lop3.b32 %0, %1, %2, %3, 0xEA;"
                        : "=r"(e[r]) : "r"(src), "r"(mask), "r"(0x64006400u));
                }
#pragma unroll
                for (int r = 0; r < 8; r++) {
                    if (c & 1)
                        asm("fma.rn.f16x2 %0, %1, %2, %3;"
                            : "=r"(e[r]) : "r"(e[r]), "r"(0x2C002C00u), "r"(zc[c]));
                    else
                        asm("sub.rn.f16x2 %0, %1, %2;"
                            : "=r"(e[r]) : "r"(e[r]), "r"(zc[c]));
                }
                const int jlo = (c + L) & 7, jhi = jlo ^ 4;
                uint32_t alo = b_s + (uint32_t)(lane * 8 + jlo) * 128 + ((uint32_t)(ko ^ jlo) << 4);
                uint32_t ahi = b_s + (uint32_t)(lane * 8 + jhi) * 128 + ((uint32_t)(ko ^ jhi) << 4);
#pragma unroll
                for (int q = 0; q < 4; q++) {
                    uint32_t lo, hi;
                    asm("prmt.b32 %0, %1, %2, 0x5410;" : "=r"(lo) : "r"(e[2*q]), "r"(e[2*q+1]));
                    asm("prmt.b32 %0, %1, %2, 0x7632;" : "=r"(hi) : "r"(e[2*q]), "r"(e[2*q+1]));
                    asm("mul.rn.f16x2 %0, %1, %2;" : "=r"(lo) : "r"(lo), "r"(s2lo[c]));
                    asm("mul.rn.f16x2 %0, %1, %2;" : "=r"(hi) : "r"(hi), "r"(s2hi[c]));
                    const uint32_t off = (uint32_t)(((q + pr) & 3) * 4);
                    asm volatile("st.shared.b32 [%0], %1;" :: "r"(alo + off), "r"(lo) : "memory");
                    asm volatile("st.shared.b32 [%0], %1;" :: "r"(ahi + off), "r"(hi) : "memory");
                }
            }
            fence_proxy_async_cta();          // generic-proxy STS -> async proxy
            mbar_arrive(mbarb + 24 + 8 * s);  // release B

            // ---- A: cp.async 8 x 16B per thread ----
            const __half* Ag = g_X + (size_t)bm * K_DIM + kt * BK;
#pragma unroll
            for (int i = 0; i < 8; i++) {
                int idx = tid + 256 * i;       // 0..2047
                int row = idx >> 3, c16 = idx & 7;
                cp_async16(a_s + row * 128 + ((c16 ^ (row & 7)) << 4),
                           Ag + (size_t)row * K_DIM + c16 * 8);
            }
            cpasync_arrive_noinc(mbarb + 8 * s);

#pragma unroll
            for (int r = 0; r < 8; r++) wq[r] = wq2[r];
        }
    } else if (elect_one()) {
        // ---------------- MMA issuer (1 thread of warp 8) ----------------
        const uint32_t idesc = (8u << 24) | (16u << 17) | (1u << 4);  // M=128,N=128,f16->f32
        for (int kt = 0; kt < KT; kt++) {
            const int s = kt % 3;
            const uint32_t par = (kt / 3) & 1;
            mbar_wait(mbarb +      8 * s, par);   // A cp.async complete
            mbar_wait(mbarb + 24 + 8 * s, par);   // B STS complete
            fence_proxy_async_cta();

            uint32_t a_s = sbase + s * STAGE_BYTES;
            uint32_t b_s = a_s + STAGE_A_BYTES;
            uint64_t ad0 = make_desc(a_s);
            uint64_t ad1 = make_desc(a_s + 16384);
            uint64_t bd0 = make_desc(b_s);
            uint64_t bd1 = make_desc(b_s + 16384);
#pragma unroll
            for (int ks = 0; ks < 4; ks++) {
                uint32_t en = (kt > 0 || ks > 0) ? 1u : 0u;
                mma_f16_ss(tmem,       ad0 + ks * 2, bd0 + ks * 2, idesc, en);
                mma_f16_ss(tmem + 128, ad0 + ks * 2, bd1 + ks * 2, idesc, en);
                mma_f16_ss(tmem + 256, ad1 + ks * 2, bd0 + ks * 2, idesc, en);
                mma_f16_ss(tmem + 384, ad1 + ks * 2, bd1 + ks * 2, idesc, en);
            }
            tc_commit(mbarb + 48 + 8 * s);     // recycle stage on MMA completion
        }
        tc_commit(mbarb + 72);
    }

    // All threads: wait for all MMAs to drain
    mbar_wait(mbarb + 72, 0);
    asm volatile("tcgen05.fence::after_thread_sync;" ::: "memory");

    // Epilogue (warps 0-7): warp w -> M-half (w>>2), rows (w&3)*32
    if (wid < 8) {
        const int h   = wid >> 2;
        const int row = bm + h * 128 + (wid & 3) * 32 + lane;
        float* dst = Out + (size_t)row * N_DIM + bn;
        const uint32_t tm = tmem + h * 256;
#pragma unroll
        for (int b = 0; b < 8; b++) {
            uint32_t v[32];
            ldtm_x32(v, tm + b * 32);
            asm volatile("tcgen05.wait::ld.sync.aligned;" ::: "memory");
#pragma unroll
            for (int i = 0; i < 8; i++) {
                float4 f;
                f.x = __uint_as_float(v[4 * i + 0]);
                f.y = __uint_as_float(v[4 * i + 1]);
                f.z = __uint_as_float(v[4 * i + 2]);
                f.w = __uint_as_float(v[4 * i + 3]);
                *reinterpret_cast<float4*>(dst + b * 32 + i * 4) = f;
            }
        }
    }
    __syncthreads();
    if (wid == 8) {
        asm volatile("tcgen05.dealloc.cta_group::1.sync.aligned.b32 %0, %1;"
                     :: "r"(tmem), "r"(512));
    }
#endif  // TC_LIVE
}

// ---------------------------------------------------------------------------
extern "C" void kernel_launch(void* const* d_in, const int* in_sizes, int n_in,
                              void* d_out, int out_size) {
    const float* x  = (const float*)d_in[0];   // [4,2048,4096] fp32 (upcast fp16)
    const int*   qw = (const int*)d_in[1];     // [4096,1376]
    const int*   qz = (const int*)d_in[2];     // [32,1376]
    const float* sc = (const float*)d_in[3];   // [32,11008] fp32 (upcast fp16)
    float* out = (float*)d_out;                // [4,2048,11008] fp32

    cudaFuncSetAttribute(gemm_tc_kernel, cudaFuncAttributeMaxDynamicSharedMemorySize,
                         SMEM_TOTAL);

    const int x_total = in_sizes[0];
    convert_x_kernel<<<(x_total / 4 + 255) / 256, 256>>>(x, x_total);

    dim3 grid(M_DIM / BM, N_DIM / BN);         // (32, 43)
    gemm_tc_kernel<<<grid, 288, SMEM_TOTAL>>>(qw, qz, sc, out);
}

// round 12
// speedup vs baseline: 1.2308x; 1.1921x over previous
#include <cuda_runtime.h>
#include <cuda.h>
#include <cuda_fp16.h>
#include <cstdint>

// Problem constants
#define M_DIM 8192
#define K_DIM 4096
#define N_DIM 11008
#define NP    (N_DIM / 8)

// tcgen05 GEMM: CTA tile 256x256, BK=64, 3 stages, TMA + 2-CTA cluster with
// B-tile multicast (cooperative slicing). Dequant is a separate pass (no 32x
// redundant ALU).
#define BM 256
#define BN 256
#define BK 64
#define STAGE_A_BYTES (BM * BK * 2)                     // 32768
#define STAGE_B_BYTES (BN * BK * 2)                     // 32768
#define STAGE_BYTES   (STAGE_A_BYTES + STAGE_B_BYTES)   // 65536
#define SMEM_STAGES   (3 * STAGE_BYTES)                 // 196608
#define SMEM_TOTAL    (SMEM_STAGES + 1024 + 128)

// Static device scratch
__device__ __half g_Wt[(size_t)N_DIM * K_DIM];  // W transposed [N][K], fp16
__device__ __half g_X [(size_t)M_DIM * K_DIM];  // activations fp16

// ---------------------------------------------------------------------------
// Pass 0: x fp32 -> fp16 (lossless; harness upcast of original fp16)
// ---------------------------------------------------------------------------
__global__ void convert_x_kernel(const float* __restrict__ x, int total) {
    int i = (blockIdx.x * blockDim.x + threadIdx.x) * 4;
    if (i >= total) return;
    float4 v = *reinterpret_cast<const float4*>(x + i);
    __half h[4];
    h[0] = __float2half(v.x); h[1] = __float2half(v.y);
    h[2] = __float2half(v.z); h[3] = __float2half(v.w);
    *reinterpret_cast<uint2*>(&g_X[i]) = *reinterpret_cast<uint2*>(h);
}

// ---------------------------------------------------------------------------
// Pass 1: dequant AWQ int4 -> fp16 transposed g_Wt[n][k] (proven R6 version)
// ---------------------------------------------------------------------------
__global__ __launch_bounds__(256)
void dequant_t_kernel(const int* __restrict__ qweight,
                      const int* __restrict__ qzeros,
                      const float* __restrict__ scales) {
    __shared__ __half s[256][64];
    const int k0 = blockIdx.x * 64;
    const int n0 = blockIdx.y * 256;
    const int g  = k0 >> 7;
    const int c0 = n0 >> 3;
    const int tid = threadIdx.x;

#pragma unroll
    for (int i = 0; i < 8; i++) {
        int lin = tid + 256 * i;
        int cl  = lin & 31;
        int kl  = lin >> 5;
        uint32_t w = (uint32_t)qweight[(size_t)(k0 + kl) * NP + c0 + cl];
        uint32_t z = (uint32_t)qzeros[(size_t)g * NP + c0 + cl];
        const float* sp = scales + (size_t)g * N_DIM + n0 + cl * 8;
#pragma unroll
        for (int j = 0; j < 8; j++) {
            float wi = (float)((w >> (4 * j)) & 15u);
            float zi = (float)((z >> (4 * j)) & 15u);
            __half v = __float2half((wi - zi) * sp[j]);
            int nl = cl * 8 + j;
            int phys16 = (kl >> 3) ^ ((nl >> 3) & 7);
            s[nl][(phys16 << 3) | (kl & 7)] = v;
        }
    }
    __syncthreads();
#pragma unroll
    for (int i = 0; i < 8; i++) {
        int idx = tid + 256 * i;
        int r = idx >> 3, q = idx & 7;
        int phys16 = q ^ ((r >> 3) & 7);
        uint4 v = *reinterpret_cast<uint4*>(&s[r][phys16 << 3]);
        *reinterpret_cast<uint4*>(&g_Wt[(size_t)(n0 + r) * K_DIM + k0 + q * 8]) = v;
    }
}

// ---------------------------------------------------------------------------
// tcgen05 / TMA helpers (device pass targets sm_103a family)
// ---------------------------------------------------------------------------
#if defined(__CUDA_ARCH__) && (defined(__CUDA_ARCH_FEAT_SM103_ALL) || defined(__CUDA_ARCH_FEAT_SM100_ALL) || defined(__CUDA_ARCH_FEAT_SM101_ALL))
#define TC_LIVE 1
#endif

#ifdef TC_LIVE
__device__ __forceinline__ uint32_t elect_one() {
    uint32_t p;
    asm volatile("{\n\t.reg .pred P;\n\telect.sync _|P, 0xFFFFFFFF;\n\t"
                 "selp.b32 %0, 1, 0, P;\n\t}" : "=r"(p));
    return p;
}
__device__ __forceinline__ uint32_t cluster_rank() {
    uint32_t r;
    asm("mov.u32 %0, %%cluster_ctarank;" : "=r"(r));
    return r;
}
__device__ __forceinline__ void mbar_init(uint32_t a, uint32_t cnt) {
    asm volatile("mbarrier.init.shared.b64 [%0], %1;" :: "r"(a), "r"(cnt) : "memory");
}
__device__ __forceinline__ void mbar_wait(uint32_t a, uint32_t parity) {
    asm volatile("{\n\t.reg .pred P;\n\tLW%=:\n\t"
                 "mbarrier.try_wait.parity.acquire.cta.shared::cta.b64 P, [%0], %1;\n\t"
                 "@!P bra LW%=;\n\t}" :: "r"(a), "r"(parity) : "memory");
}
__device__ __forceinline__ void mbar_expect_tx(uint32_t a, uint32_t bytes) {
    asm volatile("mbarrier.arrive.expect_tx.shared.b64 _, [%0], %1;"
                 :: "r"(a), "r"(bytes) : "memory");
}
__device__ __forceinline__ void tma_2d(uint32_t dst, const void* map,
                                       int32_t x, int32_t y, uint32_t mbar) {
    asm volatile("cp.async.bulk.tensor.2d.shared::cta.global.tile"
                 ".mbarrier::complete_tx::bytes [%0], [%1, {%2, %3}], [%4];"
                 :: "r"(dst), "l"(map), "r"(x), "r"(y), "r"(mbar) : "memory");
}
__device__ __forceinline__ void tma_2d_mc(uint32_t dst, const void* map,
                                          int32_t x, int32_t y, uint32_t mbar,
                                          uint16_t mask) {
    asm volatile("cp.async.bulk.tensor.2d.shared::cluster.global.tile"
                 ".mbarrier::complete_tx::bytes.multicast::cluster "
                 "[%0], [%1, {%2, %3}], [%4], %5;"
                 :: "r"(dst), "l"(map), "r"(x), "r"(y), "r"(mbar), "h"(mask)
                 : "memory");
}
__device__ __forceinline__ void tc_commit(uint32_t mbar) {
    asm volatile("tcgen05.commit.cta_group::1.mbarrier::arrive::one.shared::cluster.b64 [%0];"
                 :: "r"(mbar) : "memory");
}
__device__ __forceinline__ void tc_commit_mc(uint32_t mbar, uint16_t mask) {
    asm volatile("tcgen05.commit.cta_group::1.mbarrier::arrive::one"
                 ".shared::cluster.multicast::cluster.b64 [%0], %1;"
                 :: "r"(mbar), "h"(mask) : "memory");
}
__device__ __forceinline__ void mma_f16_ss(uint32_t d, uint64_t ad, uint64_t bd,
                                           uint32_t idesc, uint32_t en) {
    asm volatile("{\n\t.reg .pred p;\n\tsetp.ne.u32 p, %4, 0;\n\t"
                 "tcgen05.mma.cta_group::1.kind::f16 [%0], %1, %2, %3, {%5,%5,%5,%5}, p;\n\t}"
                 :: "r"(d), "l"(ad), "l"(bd), "r"(idesc), "r"(en), "r"(0u) : "memory");
}
// K-major SW128 descriptor: layout=2, version=1, SBO=64, LBO=1 (proven)
__device__ __forceinline__ uint64_t make_desc(uint32_t smem_addr) {
    return ((uint64_t)2 << 61) | ((uint64_t)1 << 46) | ((uint64_t)64 << 32) |
           ((uint64_t)1 << 16) | (((uint64_t)(smem_addr >> 4)) & 0x3FFF);
}
__device__ __forceinline__ void ldtm_x32(uint32_t* r, uint32_t tmem) {
    asm volatile(
        "tcgen05.ld.sync.aligned.32x32b.x32.b32 "
        "{%0,%1,%2,%3,%4,%5,%6,%7,%8,%9,%10,%11,%12,%13,%14,%15,"
        "%16,%17,%18,%19,%20,%21,%22,%23,%24,%25,%26,%27,%28,%29,%30,%31}, [%32];"
        : "=r"(r[0]),"=r"(r[1]),"=r"(r[2]),"=r"(r[3]),"=r"(r[4]),"=r"(r[5]),"=r"(r[6]),"=r"(r[7]),
          "=r"(r[8]),"=r"(r[9]),"=r"(r[10]),"=r"(r[11]),"=r"(r[12]),"=r"(r[13]),"=r"(r[14]),"=r"(r[15]),
          "=r"(r[16]),"=r"(r[17]),"=r"(r[18]),"=r"(r[19]),"=r"(r[20]),"=r"(r[21]),"=r"(r[22]),"=r"(r[23]),
          "=r"(r[24]),"=r"(r[25]),"=r"(r[26]),"=r"(r[27]),"=r"(r[28]),"=r"(r[29]),"=r"(r[30]),"=r"(r[31])
        : "r"(tmem));
}
#endif  // TC_LIVE

// 288 threads. Warp 0 elect = TMA producer; warp 8 elect = MMA issuer;
// warps 0-7 = epilogue. Cluster (2,1,1): pair shares the B tile (same bn,
// adjacent bm); each CTA loads one 128-row slice and multicasts it.
__global__ __launch_bounds__(288, 1) __cluster_dims__(2, 1, 1)
void gemm_tc_kernel(const __grid_constant__ CUtensorMap tma_a,
                    const __grid_constant__ CUtensorMap tma_b,
                    float* __restrict__ Out) {
#ifdef TC_LIVE
    extern __shared__ char smem_raw[];
    char* smem = (char*)(((uintptr_t)smem_raw + 1023) & ~(uintptr_t)1023);
    const uint32_t sbase = (uint32_t)__cvta_generic_to_shared(smem);
    const uint32_t mbarb = sbase + SMEM_STAGES;
    // full[s]: +0,+8,+16 ; empty[s]: +24,+32,+40 ; fin: +48 ; tmem ptr: +56

    const int tid  = threadIdx.x;
    const int wid  = tid >> 5;
    const int lane = tid & 31;
    const uint32_t rank = cluster_rank();
    const int bm = blockIdx.x * BM;
    const int bn = blockIdx.y * BN;

    if (tid == 0) {
#pragma unroll
        for (int s = 0; s < 3; s++) {
            mbar_init(mbarb +      8 * s, 1);    // full: 1 expect_tx arrival
            mbar_init(mbarb + 24 + 8 * s, 2);    // empty: 2 commits (both CTAs)
        }
        mbar_init(mbarb + 48, 1);                // fin
    }
    if (wid == 8) {
        asm volatile("tcgen05.alloc.cta_group::1.sync.aligned.shared::cta.b32 [%0], %1;"
                     :: "r"(mbarb + 56), "r"(512) : "memory");
        asm volatile("tcgen05.relinquish_alloc_permit.cta_group::1.sync.aligned;");
    }
    __syncthreads();
    // Both CTAs' barriers must exist before any multicast TMA / commit.
    asm volatile("barrier.cluster.arrive.aligned;" ::: "memory");
    asm volatile("barrier.cluster.wait.aligned;" ::: "memory");

    uint32_t tmem;
    asm volatile("ld.shared.b32 %0, [%1];" : "=r"(tmem) : "r"(mbarb + 56));

    const int KT = K_DIM / BK;  // 64

    if (wid == 0 && elect_one()) {
        // ---------------- TMA producer (1 thread) ----------------
        for (int kt = 0; kt < KT; kt++) {
            const int s = kt % 3;
            const uint32_t e_par = ((kt / 3) & 1) ^ 1;   // first 3 uses pass
            mbar_wait(mbarb + 24 + 8 * s, e_par);

            const uint32_t full = mbarb + 8 * s;
            mbar_expect_tx(full, STAGE_BYTES);           // A 32KB + B 2x16KB
            uint32_t a_s = sbase + s * STAGE_BYTES;
            uint32_t b_s = a_s + STAGE_A_BYTES;
            // A: own 256 rows, own smem, own barrier
            tma_2d(a_s, &tma_a, kt * BK, bm, full);
            // B: cooperative slice (rank's 128 rows), multicast to both CTAs
            tma_2d_mc(b_s + rank * 16384, &tma_b,
                      kt * BK, bn + (int)rank * 128, full, (uint16_t)0x3);
        }
    } else if (wid == 8 && elect_one()) {
        // ---------------- MMA issuer (1 thread) ----------------
        const uint32_t idesc = (8u << 24) | (16u << 17) | (1u << 4);  // M=128,N=128,f16->f32
        for (int kt = 0; kt < KT; kt++) {
            const int s = kt % 3;
            mbar_wait(mbarb + 8 * s, (kt / 3) & 1);

            uint32_t a_s = sbase + s * STAGE_BYTES;
            uint32_t b_s = a_s + STAGE_A_BYTES;
            uint64_t ad0 = make_desc(a_s);
            uint64_t ad1 = make_desc(a_s + 16384);
            uint64_t bd0 = make_desc(b_s);
            uint64_t bd1 = make_desc(b_s + 16384);
#pragma unroll
            for (int ks = 0; ks < 4; ks++) {
                uint32_t en = (kt > 0 || ks > 0) ? 1u : 0u;
                mma_f16_ss(tmem,       ad0 + ks * 2, bd0 + ks * 2, idesc, en);
                mma_f16_ss(tmem + 128, ad0 + ks * 2, bd1 + ks * 2, idesc, en);
                mma_f16_ss(tmem + 256, ad1 + ks * 2, bd0 + ks * 2, idesc, en);
                mma_f16_ss(tmem + 384, ad1 + ks * 2, bd1 + ks * 2, idesc, en);
            }
            // Recycle stage in BOTH CTAs when this CTA's MMAs complete.
            tc_commit_mc(mbarb + 24 + 8 * s, (uint16_t)0x3);
        }
        tc_commit(mbarb + 48);
    }

    // All threads: wait for all MMAs to drain
    mbar_wait(mbarb + 48, 0);
    asm volatile("tcgen05.fence::after_thread_sync;" ::: "memory");

    // Epilogue (warps 0-7): warp w -> M-half (w>>2), rows (w&3)*32
    if (wid < 8) {
        const int h   = wid >> 2;
        const int row = bm + h * 128 + (wid & 3) * 32 + lane;
        float* dst = Out + (size_t)row * N_DIM + bn;
        const uint32_t tm = tmem + h * 256;
#pragma unroll
        for (int b = 0; b < 8; b++) {
            uint32_t v[32];
            ldtm_x32(v, tm + b * 32);
            asm volatile("tcgen05.wait::ld.sync.aligned;" ::: "memory");
#pragma unroll
            for (int i = 0; i < 8; i++) {
                float4 f;
                f.x = __uint_as_float(v[4 * i + 0]);
                f.y = __uint_as_float(v[4 * i + 1]);
                f.z = __uint_as_float(v[4 * i + 2]);
                f.w = __uint_as_float(v[4 * i + 3]);
                *reinterpret_cast<float4*>(dst + b * 32 + i * 4) = f;
            }
        }
    }
    __syncthreads();
    if (wid == 8) {
        asm volatile("tcgen05.dealloc.cta_group::1.sync.aligned.b32 %0, %1;"
                     :: "r"(tmem), "r"(512));
    }
    // No CTA may exit while the peer could still multicast into its smem.
    asm volatile("barrier.cluster.arrive.aligned;" ::: "memory");
    asm volatile("barrier.cluster.wait.aligned;" ::: "memory");
#endif  // TC_LIVE
}

// ---------------------------------------------------------------------------
typedef CUresult (*EncodeTiledFn)(
    CUtensorMap*, CUtensorMapDataType, cuuint32_t, void*,
    const cuuint64_t*, const cuuint64_t*, const cuuint32_t*, const cuuint32_t*,
    CUtensorMapInterleave, CUtensorMapSwizzle, CUtensorMapL2promotion,
    CUtensorMapFloatOOBfill);

extern "C" void kernel_launch(void* const* d_in, const int* in_sizes, int n_in,
                              void* d_out, int out_size) {
    const float* x  = (const float*)d_in[0];   // [4,2048,4096] fp32 (upcast fp16)
    const int*   qw = (const int*)d_in[1];     // [4096,1376]
    const int*   qz = (const int*)d_in[2];     // [32,1376]
    const float* sc = (const float*)d_in[3];   // [32,11008] fp32 (upcast fp16)
    float* out = (float*)d_out;                // [4,2048,11008] fp32

    cudaFuncSetAttribute(gemm_tc_kernel, cudaFuncAttributeMaxDynamicSharedMemorySize,
                         SMEM_TOTAL);

    // Build TMA descriptors for g_X [M,K] and g_Wt [N,K] (SW128, fp16).
    void* pX = nullptr; void* pW = nullptr;
    cudaGetSymbolAddress(&pX, g_X);
    cudaGetSymbolAddress(&pW, g_Wt);
    EncodeTiledFn enc = nullptr;
    cudaDriverEntryPointQueryResult qr;
    cudaGetDriverEntryPointByVersion("cuTensorMapEncodeTiled", (void**)&enc,
                                     12000, cudaEnableDefault, &qr);
    CUtensorMap ta, tb;
    {
        cuuint64_t dims[2] = {K_DIM, M_DIM};
        cuuint64_t strides[1] = {K_DIM * 2};
        cuuint32_t box[2] = {BK, BM};            // 64 x 256 (box0 = 128B = SW128)
        cuuint32_t es[2] = {1, 1};
        enc(&ta, CU_TENSOR_MAP_DATA_TYPE_FLOAT16, 2, pX, dims, strides, box, es,
            CU_TENSOR_MAP_INTERLEAVE_NONE, CU_TENSOR_MAP_SWIZZLE_128B,
            CU_TENSOR_MAP_L2_PROMOTION_L2_128B, CU_TENSOR_MAP_FLOAT_OOB_FILL_NONE);
    }
    {
        cuuint64_t dims[2] = {K_DIM, N_DIM};
        cuuint64_t strides[1] = {K_DIM * 2};
        cuuint32_t box[2] = {BK, BN / 2};        // 64 x 128 (cooperative slice)
        cuuint32_t es[2] = {1, 1};
        enc(&tb, CU_TENSOR_MAP_DATA_TYPE_FLOAT16, 2, pW, dims, strides, box, es,
            CU_TENSOR_MAP_INTERLEAVE_NONE, CU_TENSOR_MAP_SWIZZLE_128B,
            CU_TENSOR_MAP_L2_PROMOTION_L2_128B, CU_TENSOR_MAP_FLOAT_OOB_FILL_NONE);
    }

    const int x_total = in_sizes[0];
    convert_x_kernel<<<(x_total / 4 + 255) / 256, 256>>>(x, x_total);

    dim3 dq_grid(K_DIM / 64, N_DIM / 256);       // (64, 43)
    dequant_t_kernel<<<dq_grid, 256>>>(qw, qz, sc);

    dim3 grid(M_DIM / BM, N_DIM / BN);           // (32, 43); cluster pairs on x
    gemm_tc_kernel<<<grid, 288, SMEM_TOTAL>>>(ta, tb, out);
}